// round 2
// baseline (speedup 1.0000x reference)
#include <cuda_runtime.h>
#include <cstdint>
#include <cstddef>

// Problem constants
#define T_TOK   4096
#define HDIM    1024
#define IDIM    2048
#define NEXP    8
#define TOPK    2
#define NROWS_ROUTED (T_TOK * TOPK)        // 8192 (always exact)
#define NROWS_TOTAL  (NROWS_ROUTED + T_TOK) // 12288
#define ROUTER_BLOCKS (T_TOK / 8)          // 512

// Output layout (tuple flattened): routed[4096*1024], aux[1], z[1], logits[4096*8]
#define OUT_ROUTED 0
#define OUT_AUX    (T_TOK * HDIM)
#define OUT_Z      (OUT_AUX + 1)
#define OUT_LOGITS (OUT_AUX + 2)

// ---------------- scratch (__device__ globals; no runtime allocation) -------
__device__ int   g_count[NEXP];
__device__ int   g_list[NEXP * T_TOK];
__device__ float g_wgt [NEXP * T_TOK];
__device__ int   g_rowbase[NEXP + 1];
__device__ int   g_ctok[NROWS_TOTAL];
__device__ float g_cwgt[NROWS_TOTAL];
__device__ float g_pp[ROUTER_BLOCKS * NEXP];
__device__ float g_pl[ROUTER_BLOCKS];
__device__ float g_G[(size_t)NROWS_TOTAL * IDIM];   // gate -> then h
__device__ float g_U[(size_t)NROWS_TOTAL * IDIM];   // up

// ---------------- kernel 0: zero counters -----------------------------------
__global__ void zero_counts_kernel() {
    if (threadIdx.x < NEXP) g_count[threadIdx.x] = 0;
}

// ---------------- kernel 1: router -------------------------------------------
// 8 warps / block, 1 token per warp. 512 blocks.
__global__ void __launch_bounds__(256) router_kernel(
    const float* __restrict__ x, const float* __restrict__ rw,
    float* __restrict__ out)
{
    const int warp = threadIdx.x >> 5, lane = threadIdx.x & 31;
    const int t = blockIdx.x * 8 + warp;

    float acc[NEXP];
#pragma unroll
    for (int e = 0; e < NEXP; e++) acc[e] = 0.f;

    const float* xr = x + (size_t)t * HDIM;
    for (int h = lane; h < HDIM; h += 32) {
        float xv = xr[h];
        const float* r = rw + (size_t)h * NEXP;
#pragma unroll
        for (int e = 0; e < NEXP; e++) acc[e] += xv * r[e];
    }
#pragma unroll
    for (int off = 16; off > 0; off >>= 1)
#pragma unroll
        for (int e = 0; e < NEXP; e++)
            acc[e] += __shfl_xor_sync(0xFFFFFFFFu, acc[e], off);

    __shared__ float s_prob[8][NEXP];
    __shared__ float s_lse2[8];

    if (lane == 0) {
        float mx = acc[0];
#pragma unroll
        for (int e = 1; e < NEXP; e++) mx = fmaxf(mx, acc[e]);
        float p[NEXP], sum = 0.f;
#pragma unroll
        for (int e = 0; e < NEXP; e++) { p[e] = expf(acc[e] - mx); sum += p[e]; }
        float lse = logf(sum) + mx;
        s_lse2[warp] = lse * lse;
        float inv = 1.f / sum;
#pragma unroll
        for (int e = 0; e < NEXP; e++) {
            p[e] *= inv;
            s_prob[warp][e] = p[e];
            out[OUT_LOGITS + (size_t)t * NEXP + e] = acc[e];
        }
        // top-2 (strict > matches jax tie-break: lowest index wins)
        int i1 = 0;
#pragma unroll
        for (int e = 1; e < NEXP; e++) if (p[e] > p[i1]) i1 = e;
        int i2 = (i1 == 0) ? 1 : 0;
#pragma unroll
        for (int e = 0; e < NEXP; e++) if (e != i2 && e != i1 && p[e] > p[i2]) i2 = e;
        float s2 = p[i1] + p[i2];
        float w1 = p[i1] / s2, w2 = p[i2] / s2;
        int pos1 = atomicAdd(&g_count[i1], 1);
        g_list[i1 * T_TOK + pos1] = t; g_wgt[i1 * T_TOK + pos1] = w1;
        int pos2 = atomicAdd(&g_count[i2], 1);
        g_list[i2 * T_TOK + pos2] = t; g_wgt[i2 * T_TOK + pos2] = w2;
    }
    __syncthreads();
    if (threadIdx.x == 0) {
        float ps[NEXP]; float l2 = 0.f;
#pragma unroll
        for (int e = 0; e < NEXP; e++) ps[e] = 0.f;
        for (int w = 0; w < 8; w++) {
            l2 += s_lse2[w];
#pragma unroll
            for (int e = 0; e < NEXP; e++) ps[e] += s_prob[w][e];
        }
#pragma unroll
        for (int e = 0; e < NEXP; e++) g_pp[blockIdx.x * NEXP + e] = ps[e];
        g_pl[blockIdx.x] = l2;
    }
}

// ---------------- kernel 2: finalize losses + row offsets --------------------
// One block, 288 threads (9 warps). Deterministic reduction.
__global__ void finalize_kernel(float* __restrict__ out) {
    const int warp = threadIdx.x >> 5, lane = threadIdx.x & 31;
    __shared__ float red[NEXP + 1];
    if (warp < NEXP) {
        float s = 0.f;
        for (int j = 0; j < ROUTER_BLOCKS / 32; j++)
            s += g_pp[(size_t)(lane + 32 * j) * NEXP + warp];
#pragma unroll
        for (int off = 16; off > 0; off >>= 1) s += __shfl_xor_sync(0xFFFFFFFFu, s, off);
        if (lane == 0) red[warp] = s;
    } else if (warp == NEXP) {
        float s = 0.f;
        for (int j = 0; j < ROUTER_BLOCKS / 32; j++)
            s += g_pl[lane + 32 * j];
#pragma unroll
        for (int off = 16; off > 0; off >>= 1) s += __shfl_xor_sync(0xFFFFFFFFu, s, off);
        if (lane == 0) red[NEXP] = s;
    }
    __syncthreads();
    if (threadIdx.x == 0) {
        float aux = 0.f;
        int rb = 0;
        for (int e = 0; e < NEXP; e++) {
            aux += ((float)g_count[e] / (float)(T_TOK * TOPK)) * (red[e] / (float)T_TOK);
            g_rowbase[e] = rb;
            rb += g_count[e];
        }
        g_rowbase[NEXP] = NROWS_ROUTED;
        out[OUT_AUX] = (float)NEXP * aux;
        out[OUT_Z]   = red[NEXP] / (float)T_TOK;
    }
}

// ---------------- kernel 3: compact dispatch lists ---------------------------
__global__ void compact_kernel() {
    int idx = blockIdx.x * blockDim.x + threadIdx.x;   // 9*4096
    int e = idx / T_TOK, pos = idx % T_TOK;
    if (e < NEXP) {
        if (pos < g_count[e]) {
            int cr = g_rowbase[e] + pos;
            g_ctok[cr] = g_list[e * T_TOK + pos];
            g_cwgt[cr] = g_wgt[e * T_TOK + pos];
        }
    } else {
        g_ctok[NROWS_ROUTED + pos] = pos;
        g_cwgt[NROWS_ROUTED + pos] = 1.f;
    }
}

// ---------------- kernel 4/5: gathered SGEMM  C[row,:]=X[tok,:] @ W_e --------
// Tile 128x128x16, 256 threads, 8x8 microtile. K=HDIM=1024, N=IDIM=2048.
// which==0 -> C = g_G, which==1 -> C = g_U   (globals resolved DEVICE-side)
__global__ void __launch_bounds__(256) gemm_gu_kernel(
    const float* __restrict__ X, const float* __restrict__ W,
    const float* __restrict__ Wsh, int which)
{
    float* __restrict__ C = which ? g_U : g_G;
    const int e = blockIdx.z;
    const int n_e = (e < NEXP) ? g_count[e] : T_TOK;
    const int m0 = blockIdx.y * 128;
    if (m0 >= n_e) return;
    const int base = g_rowbase[e];
    const float* B = (e < NEXP) ? (W + (size_t)e * HDIM * IDIM) : Wsh;
    const int n0 = blockIdx.x * 128;
    const int tid = threadIdx.x;
    const int tx = tid & 15, ty = tid >> 4;

    __shared__ float As[16][128];
    __shared__ float Bs[16][128];

    const int lm0 = tid >> 2;            // 0..63
    const int lk0 = (tid & 3) * 4;       // 0,4,8,12
    int  tokA[2]; bool vA[2];
#pragma unroll
    for (int i = 0; i < 2; i++) {
        int m = m0 + lm0 + i * 64;
        vA[i] = (m < n_e);
        tokA[i] = vA[i] ? g_ctok[base + m] : 0;
    }
    const int bk0 = tid >> 5;            // 0..7
    const int bn0 = (tid & 31) * 4;

    float acc[8][8];
#pragma unroll
    for (int i = 0; i < 8; i++)
#pragma unroll
        for (int j = 0; j < 8; j++) acc[i][j] = 0.f;

    for (int k0 = 0; k0 < HDIM; k0 += 16) {
#pragma unroll
        for (int i = 0; i < 2; i++) {
            float4 v = vA[i] ? *(const float4*)(X + (size_t)tokA[i] * HDIM + k0 + lk0)
                             : make_float4(0.f, 0.f, 0.f, 0.f);
            As[lk0 + 0][lm0 + i * 64] = v.x;
            As[lk0 + 1][lm0 + i * 64] = v.y;
            As[lk0 + 2][lm0 + i * 64] = v.z;
            As[lk0 + 3][lm0 + i * 64] = v.w;
        }
#pragma unroll
        for (int i = 0; i < 2; i++) {
            int kk = bk0 + i * 8;
            *(float4*)&Bs[kk][bn0] =
                *(const float4*)(B + (size_t)(k0 + kk) * IDIM + n0 + bn0);
        }
        __syncthreads();
#pragma unroll
        for (int k = 0; k < 16; k++) {
            float rm[8], rn[8];
            *(float4*)rm       = *(float4*)&As[k][ty * 8];
            *(float4*)(rm + 4) = *(float4*)&As[k][ty * 8 + 4];
            *(float4*)rn       = *(float4*)&Bs[k][tx * 8];
            *(float4*)(rn + 4) = *(float4*)&Bs[k][tx * 8 + 4];
#pragma unroll
            for (int i = 0; i < 8; i++)
#pragma unroll
                for (int j = 0; j < 8; j++) acc[i][j] += rm[i] * rn[j];
        }
        __syncthreads();
    }
#pragma unroll
    for (int i = 0; i < 8; i++) {
        int m = m0 + ty * 8 + i;
        if (m < n_e) {
            float* Cr = C + (size_t)(base + m) * IDIM + n0 + tx * 8;
            *(float4*)Cr       = make_float4(acc[i][0], acc[i][1], acc[i][2], acc[i][3]);
            *(float4*)(Cr + 4) = make_float4(acc[i][4], acc[i][5], acc[i][6], acc[i][7]);
        }
    }
}

// ---------------- kernel 6: h = w * silu(g) * u ------------------------------
__global__ void act_kernel() {
    size_t idx4 = (size_t)blockIdx.x * blockDim.x + threadIdx.x;  // float4 index
    size_t base = idx4 * 4;
    int row = (int)(base / IDIM);
    float w = g_cwgt[row];
    float4 g = *(float4*)&g_G[base];
    float4 u = *(float4*)&g_U[base];
    float4 h;
    h.x = w * u.x * g.x / (1.f + __expf(-g.x));
    h.y = w * u.y * g.y / (1.f + __expf(-g.y));
    h.z = w * u.z * g.z / (1.f + __expf(-g.z));
    h.w = w * u.w * g.w / (1.f + __expf(-g.w));
    *(float4*)&g_G[base] = h;
}

// ---------------- kernel 7: down SGEMM with scatter-accumulate ---------------
// A = g_G (h, compact rows), K=IDIM=2048, N=HDIM=1024. atomicAdd into out.
__global__ void __launch_bounds__(256) gemm_down_kernel(
    const float* __restrict__ W, const float* __restrict__ Wsh,
    float* __restrict__ out)
{
    const int e = blockIdx.z;
    const int n_e = (e < NEXP) ? g_count[e] : T_TOK;
    const int m0 = blockIdx.y * 128;
    if (m0 >= n_e) return;
    const int base = g_rowbase[e];
    const float* B = (e < NEXP) ? (W + (size_t)e * IDIM * HDIM) : Wsh;
    const int n0 = blockIdx.x * 128;
    const int tid = threadIdx.x;
    const int tx = tid & 15, ty = tid >> 4;

    __shared__ float As[16][128];
    __shared__ float Bs[16][128];

    const int lm0 = tid >> 2;
    const int lk0 = (tid & 3) * 4;
    bool vA[2];
#pragma unroll
    for (int i = 0; i < 2; i++) vA[i] = (m0 + lm0 + i * 64) < n_e;
    const int bk0 = tid >> 5;
    const int bn0 = (tid & 31) * 4;

    float acc[8][8];
#pragma unroll
    for (int i = 0; i < 8; i++)
#pragma unroll
        for (int j = 0; j < 8; j++) acc[i][j] = 0.f;

    for (int k0 = 0; k0 < IDIM; k0 += 16) {
#pragma unroll
        for (int i = 0; i < 2; i++) {
            int m = m0 + lm0 + i * 64;
            float4 v = vA[i] ? *(const float4*)(g_G + (size_t)(base + m) * IDIM + k0 + lk0)
                             : make_float4(0.f, 0.f, 0.f, 0.f);
            As[lk0 + 0][lm0 + i * 64] = v.x;
            As[lk0 + 1][lm0 + i * 64] = v.y;
            As[lk0 + 2][lm0 + i * 64] = v.z;
            As[lk0 + 3][lm0 + i * 64] = v.w;
        }
#pragma unroll
        for (int i = 0; i < 2; i++) {
            int kk = bk0 + i * 8;
            *(float4*)&Bs[kk][bn0] =
                *(const float4*)(B + (size_t)(k0 + kk) * HDIM + n0 + bn0);
        }
        __syncthreads();
#pragma unroll
        for (int k = 0; k < 16; k++) {
            float rm[8], rn[8];
            *(float4*)rm       = *(float4*)&As[k][ty * 8];
            *(float4*)(rm + 4) = *(float4*)&As[k][ty * 8 + 4];
            *(float4*)rn       = *(float4*)&Bs[k][tx * 8];
            *(float4*)(rn + 4) = *(float4*)&Bs[k][tx * 8 + 4];
#pragma unroll
            for (int i = 0; i < 8; i++)
#pragma unroll
                for (int j = 0; j < 8; j++) acc[i][j] += rm[i] * rn[j];
        }
        __syncthreads();
    }
#pragma unroll
    for (int i = 0; i < 8; i++) {
        int m = m0 + ty * 8 + i;
        if (m < n_e) {
            int tok = g_ctok[base + m];
            float* o = out + (size_t)tok * HDIM + n0 + tx * 8;
#pragma unroll
            for (int j = 0; j < 8; j++) atomicAdd(o + j, acc[i][j]);
        }
    }
}

// ---------------- host launcher ----------------------------------------------
extern "C" void kernel_launch(void* const* d_in, const int* in_sizes, int n_in,
                              void* d_out, int out_size)
{
    const float* x       = (const float*)d_in[0];  // [2,2048,1024]
    const float* rw      = (const float*)d_in[1];  // [1024,8]
    const float* gate_w  = (const float*)d_in[2];  // [8,1024,2048]
    const float* up_w    = (const float*)d_in[3];  // [8,1024,2048]
    const float* down_w  = (const float*)d_in[4];  // [8,2048,1024]
    const float* sgate_w = (const float*)d_in[5];  // [1024,2048]
    const float* sup_w   = (const float*)d_in[6];  // [1024,2048]
    const float* sdown_w = (const float*)d_in[7];  // [2048,1024]
    float* out = (float*)d_out;

    // zero routed-output region (d_out is poisoned)
    cudaMemsetAsync(out, 0, (size_t)T_TOK * HDIM * sizeof(float));

    zero_counts_kernel<<<1, 32>>>();
    router_kernel<<<ROUTER_BLOCKS, 256>>>(x, rw, out);
    finalize_kernel<<<1, 288>>>(out);
    compact_kernel<<<( (NEXP + 1) * T_TOK ) / 256, 256>>>();

    dim3 grid_gu(IDIM / 128, T_TOK / 128, NEXP + 1);
    gemm_gu_kernel<<<grid_gu, 256>>>(x, gate_w, sgate_w, /*which=*/0);
    gemm_gu_kernel<<<grid_gu, 256>>>(x, up_w,   sup_w,   /*which=*/1);

    act_kernel<<<(int)(((size_t)NROWS_TOTAL * IDIM / 4) / 256), 256>>>();

    dim3 grid_dn(HDIM / 128, T_TOK / 128, NEXP + 1);
    gemm_down_kernel<<<grid_dn, 256>>>(down_w, sdown_w, out);
}

// round 3
// speedup vs baseline: 2.3566x; 2.3566x over previous
#include <cuda_runtime.h>
#include <cstdint>
#include <cstddef>

// Problem constants
#define T_TOK   4096
#define HDIM    1024
#define IDIM    2048
#define NEXP    8
#define TOPK    2
#define NROWS_ROUTED (T_TOK * TOPK)         // 8192
#define NROWS_TOTAL  (NROWS_ROUTED + T_TOK) // 12288
#define ROUTER_BLOCKS (T_TOK / 8)           // 512

// Output layout: routed[4096*1024], aux[1], z[1], logits[4096*8]
#define OUT_AUX    (T_TOK * HDIM)
#define OUT_Z      (OUT_AUX + 1)
#define OUT_LOGITS (OUT_AUX + 2)

// ---------------- scratch ----------------------------------------------------
__device__ int   g_count[NEXP];
__device__ int   g_list[NEXP * T_TOK];
__device__ float g_wgt [NEXP * T_TOK];
__device__ int   g_rowbase[NEXP + 1];
__device__ int   g_ctok[NROWS_TOTAL];
__device__ float g_cwgt[NROWS_TOTAL];
__device__ float g_pp[ROUTER_BLOCKS * NEXP];
__device__ float g_pl[ROUTER_BLOCKS];
__device__ float g_G[(size_t)NROWS_TOTAL * IDIM];   // gate -> then h
__device__ float g_U[(size_t)NROWS_TOTAL * IDIM];   // up

// ---------------- small helpers ----------------------------------------------
__device__ __forceinline__ uint32_t f2tf32(float f) {
    uint32_t r;
    asm("cvt.rna.tf32.f32 %0, %1;" : "=r"(r) : "f"(f));
    return r;
}
__device__ __forceinline__ void cp_async16(uint32_t s, const void* g) {
    asm volatile("cp.async.cg.shared.global [%0], [%1], 16;\n" :: "r"(s), "l"(g));
}
__device__ __forceinline__ void cp_commit() {
    asm volatile("cp.async.commit_group;\n");
}
template <int N>
__device__ __forceinline__ void cp_wait() {
    asm volatile("cp.async.wait_group %0;\n" :: "n"(N));
}
__device__ __forceinline__ void mma_tf32(float* d, const uint32_t* a, const uint32_t* b) {
    asm volatile(
        "mma.sync.aligned.m16n8k8.row.col.f32.tf32.tf32.f32 "
        "{%0,%1,%2,%3},{%4,%5,%6,%7},{%8,%9},{%0,%1,%2,%3};"
        : "+f"(d[0]), "+f"(d[1]), "+f"(d[2]), "+f"(d[3])
        : "r"(a[0]), "r"(a[1]), "r"(a[2]), "r"(a[3]), "r"(b[0]), "r"(b[1]));
}

// ---------------- kernel 0: zero counters ------------------------------------
__global__ void zero_counts_kernel() {
    if (threadIdx.x < NEXP) g_count[threadIdx.x] = 0;
}

// ---------------- kernel 1: router -------------------------------------------
__global__ void __launch_bounds__(256) router_kernel(
    const float* __restrict__ x, const float* __restrict__ rw,
    float* __restrict__ out)
{
    const int warp = threadIdx.x >> 5, lane = threadIdx.x & 31;
    const int t = blockIdx.x * 8 + warp;

    float acc[NEXP];
#pragma unroll
    for (int e = 0; e < NEXP; e++) acc[e] = 0.f;

    const float* xr = x + (size_t)t * HDIM;
    for (int h = lane; h < HDIM; h += 32) {
        float xv = xr[h];
        const float* r = rw + (size_t)h * NEXP;
#pragma unroll
        for (int e = 0; e < NEXP; e++) acc[e] += xv * r[e];
    }
#pragma unroll
    for (int off = 16; off > 0; off >>= 1)
#pragma unroll
        for (int e = 0; e < NEXP; e++)
            acc[e] += __shfl_xor_sync(0xFFFFFFFFu, acc[e], off);

    __shared__ float s_prob[8][NEXP];
    __shared__ float s_lse2[8];

    if (lane == 0) {
        float mx = acc[0];
#pragma unroll
        for (int e = 1; e < NEXP; e++) mx = fmaxf(mx, acc[e]);
        float p[NEXP], sum = 0.f;
#pragma unroll
        for (int e = 0; e < NEXP; e++) { p[e] = expf(acc[e] - mx); sum += p[e]; }
        float lse = logf(sum) + mx;
        s_lse2[warp] = lse * lse;
        float inv = 1.f / sum;
#pragma unroll
        for (int e = 0; e < NEXP; e++) {
            p[e] *= inv;
            s_prob[warp][e] = p[e];
            out[OUT_LOGITS + (size_t)t * NEXP + e] = acc[e];
        }
        int i1 = 0;
#pragma unroll
        for (int e = 1; e < NEXP; e++) if (p[e] > p[i1]) i1 = e;
        int i2 = (i1 == 0) ? 1 : 0;
#pragma unroll
        for (int e = 0; e < NEXP; e++) if (e != i2 && e != i1 && p[e] > p[i2]) i2 = e;
        float s2 = p[i1] + p[i2];
        float w1 = p[i1] / s2, w2 = p[i2] / s2;
        int pos1 = atomicAdd(&g_count[i1], 1);
        g_list[i1 * T_TOK + pos1] = t; g_wgt[i1 * T_TOK + pos1] = w1;
        int pos2 = atomicAdd(&g_count[i2], 1);
        g_list[i2 * T_TOK + pos2] = t; g_wgt[i2 * T_TOK + pos2] = w2;
    }
    __syncthreads();
    if (threadIdx.x == 0) {
        float ps[NEXP]; float l2 = 0.f;
#pragma unroll
        for (int e = 0; e < NEXP; e++) ps[e] = 0.f;
        for (int w = 0; w < 8; w++) {
            l2 += s_lse2[w];
#pragma unroll
            for (int e = 0; e < NEXP; e++) ps[e] += s_prob[w][e];
        }
#pragma unroll
        for (int e = 0; e < NEXP; e++) g_pp[blockIdx.x * NEXP + e] = ps[e];
        g_pl[blockIdx.x] = l2;
    }
}

// ---------------- kernel 2: finalize losses + row offsets --------------------
__global__ void finalize_kernel(float* __restrict__ out) {
    const int warp = threadIdx.x >> 5, lane = threadIdx.x & 31;
    __shared__ float red[NEXP + 1];
    if (warp < NEXP) {
        float s = 0.f;
        for (int j = 0; j < ROUTER_BLOCKS / 32; j++)
            s += g_pp[(size_t)(lane + 32 * j) * NEXP + warp];
#pragma unroll
        for (int off = 16; off > 0; off >>= 1) s += __shfl_xor_sync(0xFFFFFFFFu, s, off);
        if (lane == 0) red[warp] = s;
    } else if (warp == NEXP) {
        float s = 0.f;
        for (int j = 0; j < ROUTER_BLOCKS / 32; j++)
            s += g_pl[lane + 32 * j];
#pragma unroll
        for (int off = 16; off > 0; off >>= 1) s += __shfl_xor_sync(0xFFFFFFFFu, s, off);
        if (lane == 0) red[NEXP] = s;
    }
    __syncthreads();
    if (threadIdx.x == 0) {
        float aux = 0.f;
        int rb = 0;
        for (int e = 0; e < NEXP; e++) {
            aux += ((float)g_count[e] / (float)(T_TOK * TOPK)) * (red[e] / (float)T_TOK);
            g_rowbase[e] = rb;
            rb += g_count[e];
        }
        g_rowbase[NEXP] = NROWS_ROUTED;
        out[OUT_AUX] = (float)NEXP * aux;
        out[OUT_Z]   = red[NEXP] / (float)T_TOK;
    }
}

// ---------------- kernel 3: compact dispatch lists ---------------------------
__global__ void compact_kernel() {
    int idx = blockIdx.x * blockDim.x + threadIdx.x;
    int e = idx / T_TOK, pos = idx % T_TOK;
    if (e < NEXP) {
        if (pos < g_count[e]) {
            int cr = g_rowbase[e] + pos;
            g_ctok[cr] = g_list[e * T_TOK + pos];
            g_cwgt[cr] = g_wgt[e * T_TOK + pos];
        }
    } else {
        g_ctok[NROWS_ROUTED + pos] = pos;
        g_cwgt[NROWS_ROUTED + pos] = 1.f;
    }
}

// ============================================================================
// TF32 tensor-core GEMMs.
// Block tile 128x128, 4 warps, each warp 64x64 (4 m-subtiles x 8 n-subtiles
// of m16n8k8). K-tile 16, cp.async double buffered.
// SMEM: As [m][k] ldk=20 (pad), Bs [k][n] ldn=132 (pad). Both conflict-free
// for the tf32 fragment pattern and 16B-aligned rows for cp.async.
// ============================================================================
#define LDK 20
#define LDN 132

// ---------------- kernel 4/5: gathered gate/up GEMM --------------------------
// C[row,:] = X[tok,:] @ B  with B [HDIM,IDIM]. which: 0->g_G, 1->g_U.
__global__ void __launch_bounds__(128, 2) gemm_gu_tf32(
    const float* __restrict__ X, const float* __restrict__ W,
    const float* __restrict__ Wsh, int which)
{
    float* __restrict__ C = which ? g_U : g_G;
    const int e = blockIdx.z;
    const int n_e = (e < NEXP) ? g_count[e] : T_TOK;
    const int m0 = blockIdx.y * 128;
    if (m0 >= n_e) return;
    const int base = g_rowbase[e];
    const float* __restrict__ B = (e < NEXP) ? (W + (size_t)e * HDIM * IDIM) : Wsh;
    const int n0 = blockIdx.x * 128;

    const int tid  = threadIdx.x;
    const int warp = tid >> 5, lane = tid & 31;
    const int gi = lane >> 2, tig = lane & 3;
    const int wm = (warp & 1) * 64, wn = (warp >> 1) * 64;

    __shared__ float As[2][128 * LDK];
    __shared__ float Bs[2][16 * LDN];

    // this thread's A-load row
    const int mrow = m0 + tid;
    const float* arow;
    {
        int tok = (mrow < n_e) ? g_ctok[base + mrow] : g_ctok[base];
        arow = X + (size_t)tok * HDIM;
    }
    uint32_t asb[2], bsb[2];
    asb[0] = (uint32_t)__cvta_generic_to_shared(&As[0][0]);
    asb[1] = (uint32_t)__cvta_generic_to_shared(&As[1][0]);
    bsb[0] = (uint32_t)__cvta_generic_to_shared(&Bs[0][0]);
    bsb[1] = (uint32_t)__cvta_generic_to_shared(&Bs[1][0]);

    float d[4][8][4];
#pragma unroll
    for (int i = 0; i < 4; i++)
#pragma unroll
        for (int j = 0; j < 8; j++)
#pragma unroll
            for (int c = 0; c < 4; c++) d[i][j][c] = 0.f;

    auto issue_tile = [&](int kt, int buf) {
        const int k0 = kt * 16;
#pragma unroll
        for (int c = 0; c < 4; c++)
            cp_async16(asb[buf] + (uint32_t)(tid * LDK + c * 4) * 4, arow + k0 + c * 4);
#pragma unroll
        for (int c = 0; c < 4; c++) {
            int idx = c * 128 + tid;
            int bk = idx >> 5, bn = (idx & 31) * 4;
            cp_async16(bsb[buf] + (uint32_t)(bk * LDN + bn) * 4,
                       B + (size_t)(k0 + bk) * IDIM + n0 + bn);
        }
        cp_commit();
    };

    const int NK = HDIM / 16;   // 64
    issue_tile(0, 0);
    for (int kt = 0; kt < NK; kt++) {
        const int buf = kt & 1;
        if (kt + 1 < NK) { issue_tile(kt + 1, buf ^ 1); cp_wait<1>(); }
        else             { cp_wait<0>(); }
        __syncthreads();
#pragma unroll
        for (int ks = 0; ks < 2; ks++) {
            const int kb = ks * 8;
            uint32_t af[4][4], bf[8][2];
#pragma unroll
            for (int ms = 0; ms < 4; ms++) {
                const int mB = wm + ms * 16;
                af[ms][0] = f2tf32(As[buf][(mB + gi)     * LDK + kb + tig]);
                af[ms][1] = f2tf32(As[buf][(mB + 8 + gi) * LDK + kb + tig]);
                af[ms][2] = f2tf32(As[buf][(mB + gi)     * LDK + kb + tig + 4]);
                af[ms][3] = f2tf32(As[buf][(mB + 8 + gi) * LDK + kb + tig + 4]);
            }
#pragma unroll
            for (int ns = 0; ns < 8; ns++) {
                const int nB = wn + ns * 8 + gi;
                bf[ns][0] = f2tf32(Bs[buf][(kb + tig)     * LDN + nB]);
                bf[ns][1] = f2tf32(Bs[buf][(kb + tig + 4) * LDN + nB]);
            }
#pragma unroll
            for (int ms = 0; ms < 4; ms++)
#pragma unroll
                for (int ns = 0; ns < 8; ns++)
                    mma_tf32(d[ms][ns], af[ms], bf[ns]);
        }
        __syncthreads();
    }

    // epilogue
#pragma unroll
    for (int ms = 0; ms < 4; ms++) {
        const int r0 = m0 + wm + ms * 16 + gi;
        const int r1 = r0 + 8;
#pragma unroll
        for (int ns = 0; ns < 8; ns++) {
            const int n = n0 + wn + ns * 8 + 2 * tig;
            if (r0 < n_e)
                *(float2*)&C[(size_t)(base + r0) * IDIM + n] =
                    make_float2(d[ms][ns][0], d[ms][ns][1]);
            if (r1 < n_e)
                *(float2*)&C[(size_t)(base + r1) * IDIM + n] =
                    make_float2(d[ms][ns][2], d[ms][ns][3]);
        }
    }
}

// ---------------- kernel 6: h = w * silu(g) * u ------------------------------
__global__ void act_kernel() {
    size_t idx4 = (size_t)blockIdx.x * blockDim.x + threadIdx.x;
    size_t basei = idx4 * 4;
    int row = (int)(basei / IDIM);
    float w = g_cwgt[row];
    float4 g = *(float4*)&g_G[basei];
    float4 u = *(float4*)&g_U[basei];
    float4 h;
    h.x = w * u.x * g.x / (1.f + __expf(-g.x));
    h.y = w * u.y * g.y / (1.f + __expf(-g.y));
    h.z = w * u.z * g.z / (1.f + __expf(-g.z));
    h.w = w * u.w * g.w / (1.f + __expf(-g.w));
    *(float4*)&g_G[basei] = h;
}

// ---------------- kernel 7: down GEMM + scatter-accumulate -------------------
// A = g_G compact rows (K=IDIM), B [IDIM,HDIM]. atomicAdd into out.
__global__ void __launch_bounds__(128, 2) gemm_down_tf32(
    const float* __restrict__ W, const float* __restrict__ Wsh,
    float* __restrict__ out)
{
    const int e = blockIdx.z;
    const int n_e = (e < NEXP) ? g_count[e] : T_TOK;
    const int m0 = blockIdx.y * 128;
    if (m0 >= n_e) return;
    const int base = g_rowbase[e];
    const float* __restrict__ B = (e < NEXP) ? (W + (size_t)e * IDIM * HDIM) : Wsh;
    const int n0 = blockIdx.x * 128;

    const int tid  = threadIdx.x;
    const int warp = tid >> 5, lane = tid & 31;
    const int gi = lane >> 2, tig = lane & 3;
    const int wm = (warp & 1) * 64, wn = (warp >> 1) * 64;

    __shared__ float As[2][128 * LDK];
    __shared__ float Bs[2][16 * LDN];

    const float* arow = g_G + (size_t)(base + m0 + tid) * IDIM;  // always in-bounds

    uint32_t asb[2], bsb[2];
    asb[0] = (uint32_t)__cvta_generic_to_shared(&As[0][0]);
    asb[1] = (uint32_t)__cvta_generic_to_shared(&As[1][0]);
    bsb[0] = (uint32_t)__cvta_generic_to_shared(&Bs[0][0]);
    bsb[1] = (uint32_t)__cvta_generic_to_shared(&Bs[1][0]);

    float d[4][8][4];
#pragma unroll
    for (int i = 0; i < 4; i++)
#pragma unroll
        for (int j = 0; j < 8; j++)
#pragma unroll
            for (int c = 0; c < 4; c++) d[i][j][c] = 0.f;

    auto issue_tile = [&](int kt, int buf) {
        const int k0 = kt * 16;
#pragma unroll
        for (int c = 0; c < 4; c++)
            cp_async16(asb[buf] + (uint32_t)(tid * LDK + c * 4) * 4, arow + k0 + c * 4);
#pragma unroll
        for (int c = 0; c < 4; c++) {
            int idx = c * 128 + tid;
            int bk = idx >> 5, bn = (idx & 31) * 4;
            cp_async16(bsb[buf] + (uint32_t)(bk * LDN + bn) * 4,
                       B + (size_t)(k0 + bk) * HDIM + n0 + bn);
        }
        cp_commit();
    };

    const int NK = IDIM / 16;   // 128
    issue_tile(0, 0);
    for (int kt = 0; kt < NK; kt++) {
        const int buf = kt & 1;
        if (kt + 1 < NK) { issue_tile(kt + 1, buf ^ 1); cp_wait<1>(); }
        else             { cp_wait<0>(); }
        __syncthreads();
#pragma unroll
        for (int ks = 0; ks < 2; ks++) {
            const int kb = ks * 8;
            uint32_t af[4][4], bf[8][2];
#pragma unroll
            for (int ms = 0; ms < 4; ms++) {
                const int mB = wm + ms * 16;
                af[ms][0] = f2tf32(As[buf][(mB + gi)     * LDK + kb + tig]);
                af[ms][1] = f2tf32(As[buf][(mB + 8 + gi) * LDK + kb + tig]);
                af[ms][2] = f2tf32(As[buf][(mB + gi)     * LDK + kb + tig + 4]);
                af[ms][3] = f2tf32(As[buf][(mB + 8 + gi) * LDK + kb + tig + 4]);
            }
#pragma unroll
            for (int ns = 0; ns < 8; ns++) {
                const int nB = wn + ns * 8 + gi;
                bf[ns][0] = f2tf32(Bs[buf][(kb + tig)     * LDN + nB]);
                bf[ns][1] = f2tf32(Bs[buf][(kb + tig + 4) * LDN + nB]);
            }
#pragma unroll
            for (int ms = 0; ms < 4; ms++)
#pragma unroll
                for (int ns = 0; ns < 8; ns++)
                    mma_tf32(d[ms][ns], af[ms], bf[ns]);
        }
        __syncthreads();
    }

    // epilogue: scatter-accumulate into out
#pragma unroll
    for (int ms = 0; ms < 4; ms++) {
        const int r0 = m0 + wm + ms * 16 + gi;
        const int r1 = r0 + 8;
        if (r0 < n_e) {
            const int tok = g_ctok[base + r0];
            float* o = out + (size_t)tok * HDIM + n0 + wn;
#pragma unroll
            for (int ns = 0; ns < 8; ns++) {
                atomicAdd(o + ns * 8 + 2 * tig,     d[ms][ns][0]);
                atomicAdd(o + ns * 8 + 2 * tig + 1, d[ms][ns][1]);
            }
        }
        if (r1 < n_e) {
            const int tok = g_ctok[base + r1];
            float* o = out + (size_t)tok * HDIM + n0 + wn;
#pragma unroll
            for (int ns = 0; ns < 8; ns++) {
                atomicAdd(o + ns * 8 + 2 * tig,     d[ms][ns][2]);
                atomicAdd(o + ns * 8 + 2 * tig + 1, d[ms][ns][3]);
            }
        }
    }
}

// ---------------- host launcher ----------------------------------------------
extern "C" void kernel_launch(void* const* d_in, const int* in_sizes, int n_in,
                              void* d_out, int out_size)
{
    const float* x       = (const float*)d_in[0];
    const float* rw      = (const float*)d_in[1];
    const float* gate_w  = (const float*)d_in[2];
    const float* up_w    = (const float*)d_in[3];
    const float* down_w  = (const float*)d_in[4];
    const float* sgate_w = (const float*)d_in[5];
    const float* sup_w   = (const float*)d_in[6];
    const float* sdown_w = (const float*)d_in[7];
    float* out = (float*)d_out;

    cudaMemsetAsync(out, 0, (size_t)T_TOK * HDIM * sizeof(float));

    zero_counts_kernel<<<1, 32>>>();
    router_kernel<<<ROUTER_BLOCKS, 256>>>(x, rw, out);
    finalize_kernel<<<1, 288>>>(out);
    compact_kernel<<<((NEXP + 1) * T_TOK) / 256, 256>>>();

    dim3 grid_gu(IDIM / 128, T_TOK / 128, NEXP + 1);
    gemm_gu_tf32<<<grid_gu, 128>>>(x, gate_w, sgate_w, 0);
    gemm_gu_tf32<<<grid_gu, 128>>>(x, up_w,   sup_w,   1);

    act_kernel<<<(int)(((size_t)NROWS_TOTAL * IDIM / 4) / 256), 256>>>();

    dim3 grid_dn(HDIM / 128, T_TOK / 128, NEXP + 1);
    gemm_down_tf32<<<grid_dn, 128>>>(down_w, sdown_w, out);
}

// round 4
// speedup vs baseline: 2.6544x; 1.1264x over previous
#include <cuda_runtime.h>
#include <cstdint>
#include <cstddef>

// Problem constants
#define T_TOK   4096
#define HDIM    1024
#define IDIM    2048
#define NEXP    8
#define TOPK    2
#define NROWS_ROUTED (T_TOK * TOPK)         // 8192
#define NROWS_TOTAL  (NROWS_ROUTED + T_TOK) // 12288
#define ROUTER_BLOCKS (T_TOK / 8)           // 512

// Output layout: routed[4096*1024], aux[1], z[1], logits[4096*8]
#define OUT_AUX    (T_TOK * HDIM)
#define OUT_Z      (OUT_AUX + 1)
#define OUT_LOGITS (OUT_AUX + 2)

// ---------------- scratch ----------------------------------------------------
__device__ int   g_count[NEXP];
__device__ int   g_list[NEXP * T_TOK];
__device__ float g_wgt [NEXP * T_TOK];
__device__ int   g_rowbase[NEXP + 1];
__device__ int   g_ctok[NROWS_TOTAL];
__device__ float g_cwgt[NROWS_TOTAL];
__device__ float g_pp[ROUTER_BLOCKS * NEXP];
__device__ float g_pl[ROUTER_BLOCKS];
__device__ float g_G[(size_t)NROWS_TOTAL * IDIM];   // h (tf32-rounded)

// ---------------- small helpers ----------------------------------------------
__device__ __forceinline__ uint32_t f2tf32(float f) {
    uint32_t r;
    asm("cvt.rna.tf32.f32 %0, %1;" : "=r"(r) : "f"(f));
    return r;
}
__device__ __forceinline__ float f2tf32f(float f) {
    return __uint_as_float(f2tf32(f));
}
__device__ __forceinline__ void cp_async16(uint32_t s, const void* g) {
    asm volatile("cp.async.cg.shared.global [%0], [%1], 16;\n" :: "r"(s), "l"(g));
}
__device__ __forceinline__ void cp_commit() {
    asm volatile("cp.async.commit_group;\n");
}
template <int N>
__device__ __forceinline__ void cp_wait() {
    asm volatile("cp.async.wait_group %0;\n" :: "n"(N));
}
__device__ __forceinline__ void mma_tf32(float* d, const uint32_t* a, const uint32_t* b) {
    asm volatile(
        "mma.sync.aligned.m16n8k8.row.col.f32.tf32.tf32.f32 "
        "{%0,%1,%2,%3},{%4,%5,%6,%7},{%8,%9},{%0,%1,%2,%3};"
        : "+f"(d[0]), "+f"(d[1]), "+f"(d[2]), "+f"(d[3])
        : "r"(a[0]), "r"(a[1]), "r"(a[2]), "r"(a[3]), "r"(b[0]), "r"(b[1]));
}

// ---------------- kernel 0: zero counters ------------------------------------
__global__ void zero_counts_kernel() {
    if (threadIdx.x < NEXP) g_count[threadIdx.x] = 0;
}

// ---------------- kernel 1: router -------------------------------------------
__global__ void __launch_bounds__(256) router_kernel(
    const float* __restrict__ x, const float* __restrict__ rw,
    float* __restrict__ out)
{
    const int warp = threadIdx.x >> 5, lane = threadIdx.x & 31;
    const int t = blockIdx.x * 8 + warp;

    float acc[NEXP];
#pragma unroll
    for (int e = 0; e < NEXP; e++) acc[e] = 0.f;

    const float* xr = x + (size_t)t * HDIM;
    for (int h = lane; h < HDIM; h += 32) {
        float xv = xr[h];
        const float* r = rw + (size_t)h * NEXP;
#pragma unroll
        for (int e = 0; e < NEXP; e++) acc[e] += xv * r[e];
    }
#pragma unroll
    for (int off = 16; off > 0; off >>= 1)
#pragma unroll
        for (int e = 0; e < NEXP; e++)
            acc[e] += __shfl_xor_sync(0xFFFFFFFFu, acc[e], off);

    __shared__ float s_prob[8][NEXP];
    __shared__ float s_lse2[8];

    if (lane == 0) {
        float mx = acc[0];
#pragma unroll
        for (int e = 1; e < NEXP; e++) mx = fmaxf(mx, acc[e]);
        float p[NEXP], sum = 0.f;
#pragma unroll
        for (int e = 0; e < NEXP; e++) { p[e] = expf(acc[e] - mx); sum += p[e]; }
        float lse = logf(sum) + mx;
        s_lse2[warp] = lse * lse;
        float inv = 1.f / sum;
#pragma unroll
        for (int e = 0; e < NEXP; e++) {
            p[e] *= inv;
            s_prob[warp][e] = p[e];
            out[OUT_LOGITS + (size_t)t * NEXP + e] = acc[e];
        }
        int i1 = 0;
#pragma unroll
        for (int e = 1; e < NEXP; e++) if (p[e] > p[i1]) i1 = e;
        int i2 = (i1 == 0) ? 1 : 0;
#pragma unroll
        for (int e = 0; e < NEXP; e++) if (e != i2 && e != i1 && p[e] > p[i2]) i2 = e;
        float s2 = p[i1] + p[i2];
        float w1 = p[i1] / s2, w2 = p[i2] / s2;
        int pos1 = atomicAdd(&g_count[i1], 1);
        g_list[i1 * T_TOK + pos1] = t; g_wgt[i1 * T_TOK + pos1] = w1;
        int pos2 = atomicAdd(&g_count[i2], 1);
        g_list[i2 * T_TOK + pos2] = t; g_wgt[i2 * T_TOK + pos2] = w2;
    }
    __syncthreads();
    if (threadIdx.x == 0) {
        float ps[NEXP]; float l2 = 0.f;
#pragma unroll
        for (int e = 0; e < NEXP; e++) ps[e] = 0.f;
        for (int w = 0; w < 8; w++) {
            l2 += s_lse2[w];
#pragma unroll
            for (int e = 0; e < NEXP; e++) ps[e] += s_prob[w][e];
        }
#pragma unroll
        for (int e = 0; e < NEXP; e++) g_pp[blockIdx.x * NEXP + e] = ps[e];
        g_pl[blockIdx.x] = l2;
    }
}

// ---------------- kernel 2: finalize losses + row offsets --------------------
__global__ void finalize_kernel(float* __restrict__ out) {
    const int warp = threadIdx.x >> 5, lane = threadIdx.x & 31;
    __shared__ float red[NEXP + 1];
    if (warp < NEXP) {
        float s = 0.f;
        for (int j = 0; j < ROUTER_BLOCKS / 32; j++)
            s += g_pp[(size_t)(lane + 32 * j) * NEXP + warp];
#pragma unroll
        for (int off = 16; off > 0; off >>= 1) s += __shfl_xor_sync(0xFFFFFFFFu, s, off);
        if (lane == 0) red[warp] = s;
    } else if (warp == NEXP) {
        float s = 0.f;
        for (int j = 0; j < ROUTER_BLOCKS / 32; j++)
            s += g_pl[lane + 32 * j];
#pragma unroll
        for (int off = 16; off > 0; off >>= 1) s += __shfl_xor_sync(0xFFFFFFFFu, s, off);
        if (lane == 0) red[NEXP] = s;
    }
    __syncthreads();
    if (threadIdx.x == 0) {
        float aux = 0.f;
        int rb = 0;
        for (int e = 0; e < NEXP; e++) {
            aux += ((float)g_count[e] / (float)(T_TOK * TOPK)) * (red[e] / (float)T_TOK);
            g_rowbase[e] = rb;
            rb += g_count[e];
        }
        g_rowbase[NEXP] = NROWS_ROUTED;
        out[OUT_AUX] = (float)NEXP * aux;
        out[OUT_Z]   = red[NEXP] / (float)T_TOK;
    }
}

// ---------------- kernel 3: compact dispatch lists ---------------------------
__global__ void compact_kernel() {
    int idx = blockIdx.x * blockDim.x + threadIdx.x;
    int e = idx / T_TOK, pos = idx % T_TOK;
    if (e < NEXP) {
        if (pos < g_count[e]) {
            int cr = g_rowbase[e] + pos;
            g_ctok[cr] = g_list[e * T_TOK + pos];
            g_cwgt[cr] = g_wgt[e * T_TOK + pos];
        }
    } else {
        g_ctok[NROWS_ROUTED + pos] = pos;
        g_cwgt[NROWS_ROUTED + pos] = 1.f;
    }
}

// ============================================================================
// Fused gate+up+act GEMM. 256 thr (8 warps, 2m x 4n), block tile 128 x 128
// over BOTH weight matrices (same n-columns), warp tile 64x32 each.
// A: LDG -> cvt.rna tf32 -> pair-pack {k,k+4} -> STS. Fragments via LDS.64,
//    no in-loop CVT. Row stride 12 float2 (24 words): gi-groups tile banks.
// B: cp.async double buffered, scalar LDS + in-loop cvt (pad 136: conflict-free).
// Epilogue: h = w*silu(g)*u, rounded to tf32, written to g_G.
// ============================================================================
#define A_ST2 12     // float2 stride per A row
#define LDN   136

__global__ void __launch_bounds__(256, 1) gemm_gu_fused(
    const float* __restrict__ X,
    const float* __restrict__ Wg, const float* __restrict__ Wu,
    const float* __restrict__ Wsg, const float* __restrict__ Wsu)
{
    const int e = blockIdx.z;
    const int n_e = (e < NEXP) ? g_count[e] : T_TOK;
    const int m0 = blockIdx.y * 128;
    if (m0 >= n_e) return;
    const int base = g_rowbase[e];
    const float* __restrict__ Bg = (e < NEXP) ? (Wg + (size_t)e * HDIM * IDIM) : Wsg;
    const float* __restrict__ Bu = (e < NEXP) ? (Wu + (size_t)e * HDIM * IDIM) : Wsu;
    const int n0 = blockIdx.x * 128;

    const int tid  = threadIdx.x;
    const int warp = tid >> 5, lane = tid & 31;
    const int gi = lane >> 2, tig = lane & 3;
    const int wm = (warp & 1) * 64, wn = (warp >> 1) * 32;

    extern __shared__ float smem[];
    float2* As  = (float2*)smem;                    // 2 * 128*A_ST2 float2
    float*  Bgs = smem + 2 * 128 * A_ST2 * 2;       // 2 * 16*LDN floats
    float*  Bus = Bgs + 2 * 16 * LDN;

    uint32_t bgb = (uint32_t)__cvta_generic_to_shared(Bgs);
    uint32_t bub = (uint32_t)__cvta_generic_to_shared(Bus);

    // A producer role: 2 threads per row
    const int ar = tid >> 1, akb = (tid & 1) * 8;
    const float* arow;
    {
        int tok = (m0 + ar < n_e) ? g_ctok[base + m0 + ar] : g_ctok[base];
        arow = X + (size_t)tok * HDIM + akb;
    }

    float dg[4][4][4], du[4][4][4];
#pragma unroll
    for (int i = 0; i < 4; i++)
#pragma unroll
        for (int j = 0; j < 4; j++)
#pragma unroll
            for (int c = 0; c < 4; c++) { dg[i][j][c] = 0.f; du[i][j][c] = 0.f; }

    auto issueB = [&](int kt, int buf) {
        const int k0 = kt * 16;
#pragma unroll
        for (int c = 0; c < 2; c++) {
            int idx = c * 256 + tid;
            int bk = idx >> 5, bn = (idx & 31) * 4;
            uint32_t off = (uint32_t)(buf * 16 * LDN + bk * LDN + bn) * 4;
            cp_async16(bgb + off, Bg + (size_t)(k0 + bk) * IDIM + n0 + bn);
            cp_async16(bub + off, Bu + (size_t)(k0 + bk) * IDIM + n0 + bn);
        }
        cp_commit();
    };
    auto stsA = [&](int buf, float4 v0, float4 v1) {
        float2* dst = As + (size_t)buf * 128 * A_ST2 + ar * A_ST2 + (akb >> 1);
        dst[0] = make_float2(f2tf32f(v0.x), f2tf32f(v1.x));
        dst[1] = make_float2(f2tf32f(v0.y), f2tf32f(v1.y));
        dst[2] = make_float2(f2tf32f(v0.z), f2tf32f(v1.z));
        dst[3] = make_float2(f2tf32f(v0.w), f2tf32f(v1.w));
    };

    const int NK = HDIM / 16;   // 64
    // preamble: tile 0
    issueB(0, 0);
    float4 a0 = *(const float4*)(arow + 0);
    float4 a1 = *(const float4*)(arow + 4);
    stsA(0, a0, a1);
    cp_wait<0>();
    __syncthreads();
    a0 = *(const float4*)(arow + 16);
    a1 = *(const float4*)(arow + 20);

    for (int kt = 0; kt < NK; kt++) {
        const int b = kt & 1;
        if (kt + 1 < NK) {
            issueB(kt + 1, b ^ 1);
            stsA(b ^ 1, a0, a1);
            if (kt + 2 < NK) {
                a0 = *(const float4*)(arow + (kt + 2) * 16);
                a1 = *(const float4*)(arow + (kt + 2) * 16 + 4);
            }
        }
        // compute tile kt
        const float2* Ab = As + (size_t)b * 128 * A_ST2;
        const float*  Bgb2 = Bgs + b * 16 * LDN;
        const float*  Bub2 = Bus + b * 16 * LDN;
#pragma unroll
        for (int ks = 0; ks < 2; ks++) {
            const int kc = ks * 4 + tig;   // pair column
            const int kr = ks * 8 + tig;   // B row
            uint32_t af[4][4];
#pragma unroll
            for (int ms = 0; ms < 4; ms++) {
                const int mB = wm + ms * 16;
                float2 p0 = Ab[(mB + gi) * A_ST2 + kc];
                float2 p1 = Ab[(mB + 8 + gi) * A_ST2 + kc];
                af[ms][0] = __float_as_uint(p0.x);
                af[ms][1] = __float_as_uint(p1.x);
                af[ms][2] = __float_as_uint(p0.y);
                af[ms][3] = __float_as_uint(p1.y);
            }
            uint32_t bf[4][2];
#pragma unroll
            for (int ns = 0; ns < 4; ns++) {
                const int nB = wn + ns * 8 + gi;
                bf[ns][0] = f2tf32(Bgb2[kr * LDN + nB]);
                bf[ns][1] = f2tf32(Bgb2[(kr + 4) * LDN + nB]);
            }
#pragma unroll
            for (int ms = 0; ms < 4; ms++)
#pragma unroll
                for (int ns = 0; ns < 4; ns++)
                    mma_tf32(dg[ms][ns], af[ms], bf[ns]);
#pragma unroll
            for (int ns = 0; ns < 4; ns++) {
                const int nB = wn + ns * 8 + gi;
                bf[ns][0] = f2tf32(Bub2[kr * LDN + nB]);
                bf[ns][1] = f2tf32(Bub2[(kr + 4) * LDN + nB]);
            }
#pragma unroll
            for (int ms = 0; ms < 4; ms++)
#pragma unroll
                for (int ns = 0; ns < 4; ns++)
                    mma_tf32(du[ms][ns], af[ms], bf[ns]);
        }
        if (kt + 1 < NK) cp_wait<0>();
        __syncthreads();
    }

    // epilogue: h = w * silu(g) * u, tf32-rounded, to g_G
#pragma unroll
    for (int ms = 0; ms < 4; ms++) {
#pragma unroll
        for (int half = 0; half < 2; half++) {
            const int r = m0 + wm + ms * 16 + half * 8 + gi;
            if (r < n_e) {
                const int row = base + r;
                const float w = g_cwgt[row];
                float* C = g_G + (size_t)row * IDIM + n0 + wn;
#pragma unroll
                for (int ns = 0; ns < 4; ns++) {
                    float g0 = dg[ms][ns][2 * half],     g1 = dg[ms][ns][2 * half + 1];
                    float u0 = du[ms][ns][2 * half],     u1 = du[ms][ns][2 * half + 1];
                    float h0 = w * u0 * g0 / (1.f + __expf(-g0));
                    float h1 = w * u1 * g1 / (1.f + __expf(-g1));
                    *(float2*)(C + ns * 8 + 2 * tig) =
                        make_float2(f2tf32f(h0), f2tf32f(h1));
                }
            }
        }
    }
}

// ---------------- down GEMM + scatter-accumulate -----------------------------
// A = g_G (tf32-clean, no cvt needed), K=IDIM, B [IDIM,HDIM]. atomicAdd to out.
#define LDK 20
__global__ void __launch_bounds__(128, 2) gemm_down_tf32(
    const float* __restrict__ W, const float* __restrict__ Wsh,
    float* __restrict__ out)
{
    const int e = blockIdx.z;
    const int n_e = (e < NEXP) ? g_count[e] : T_TOK;
    const int m0 = blockIdx.y * 128;
    if (m0 >= n_e) return;
    const int base = g_rowbase[e];
    const float* __restrict__ B = (e < NEXP) ? (W + (size_t)e * IDIM * HDIM) : Wsh;
    const int n0 = blockIdx.x * 128;

    const int tid  = threadIdx.x;
    const int warp = tid >> 5, lane = tid & 31;
    const int gi = lane >> 2, tig = lane & 3;
    const int wm = (warp & 1) * 64, wn = (warp >> 1) * 64;

    __shared__ float As[2][128 * LDK];
    __shared__ float Bs[2][16 * LDN];

    const float* arow = g_G + (size_t)(base + m0 + tid) * IDIM;

    uint32_t asb[2], bsb[2];
    asb[0] = (uint32_t)__cvta_generic_to_shared(&As[0][0]);
    asb[1] = (uint32_t)__cvta_generic_to_shared(&As[1][0]);
    bsb[0] = (uint32_t)__cvta_generic_to_shared(&Bs[0][0]);
    bsb[1] = (uint32_t)__cvta_generic_to_shared(&Bs[1][0]);

    float d[4][8][4];
#pragma unroll
    for (int i = 0; i < 4; i++)
#pragma unroll
        for (int j = 0; j < 8; j++)
#pragma unroll
            for (int c = 0; c < 4; c++) d[i][j][c] = 0.f;

    auto issue_tile = [&](int kt, int buf) {
        const int k0 = kt * 16;
#pragma unroll
        for (int c = 0; c < 4; c++)
            cp_async16(asb[buf] + (uint32_t)(tid * LDK + c * 4) * 4, arow + k0 + c * 4);
#pragma unroll
        for (int c = 0; c < 4; c++) {
            int idx = c * 128 + tid;
            int bk = idx >> 5, bn = (idx & 31) * 4;
            cp_async16(bsb[buf] + (uint32_t)(bk * LDN + bn) * 4,
                       B + (size_t)(k0 + bk) * HDIM + n0 + bn);
        }
        cp_commit();
    };

    const int NK = IDIM / 16;   // 128
    issue_tile(0, 0);
    for (int kt = 0; kt < NK; kt++) {
        const int buf = kt & 1;
        if (kt + 1 < NK) { issue_tile(kt + 1, buf ^ 1); cp_wait<1>(); }
        else             { cp_wait<0>(); }
        __syncthreads();
#pragma unroll
        for (int ks = 0; ks < 2; ks++) {
            const int kb = ks * 8;
            uint32_t af[4][4], bf[8][2];
#pragma unroll
            for (int ms = 0; ms < 4; ms++) {
                const int mB = wm + ms * 16;
                af[ms][0] = __float_as_uint(As[buf][(mB + gi)     * LDK + kb + tig]);
                af[ms][1] = __float_as_uint(As[buf][(mB + 8 + gi) * LDK + kb + tig]);
                af[ms][2] = __float_as_uint(As[buf][(mB + gi)     * LDK + kb + tig + 4]);
                af[ms][3] = __float_as_uint(As[buf][(mB + 8 + gi) * LDK + kb + tig + 4]);
            }
#pragma unroll
            for (int ns = 0; ns < 8; ns++) {
                const int nB = wn + ns * 8 + gi;
                bf[ns][0] = f2tf32(Bs[buf][(kb + tig)     * LDN + nB]);
                bf[ns][1] = f2tf32(Bs[buf][(kb + tig + 4) * LDN + nB]);
            }
#pragma unroll
            for (int ms = 0; ms < 4; ms++)
#pragma unroll
                for (int ns = 0; ns < 8; ns++)
                    mma_tf32(d[ms][ns], af[ms], bf[ns]);
        }
        __syncthreads();
    }

#pragma unroll
    for (int ms = 0; ms < 4; ms++) {
        const int r0 = m0 + wm + ms * 16 + gi;
        const int r1 = r0 + 8;
        if (r0 < n_e) {
            const int tok = g_ctok[base + r0];
            float* o = out + (size_t)tok * HDIM + n0 + wn;
#pragma unroll
            for (int ns = 0; ns < 8; ns++) {
                atomicAdd(o + ns * 8 + 2 * tig,     d[ms][ns][0]);
                atomicAdd(o + ns * 8 + 2 * tig + 1, d[ms][ns][1]);
            }
        }
        if (r1 < n_e) {
            const int tok = g_ctok[base + r1];
            float* o = out + (size_t)tok * HDIM + n0 + wn;
#pragma unroll
            for (int ns = 0; ns < 8; ns++) {
                atomicAdd(o + ns * 8 + 2 * tig,     d[ms][ns][2]);
                atomicAdd(o + ns * 8 + 2 * tig + 1, d[ms][ns][3]);
            }
        }
    }
}

// ---------------- host launcher ----------------------------------------------
extern "C" void kernel_launch(void* const* d_in, const int* in_sizes, int n_in,
                              void* d_out, int out_size)
{
    const float* x       = (const float*)d_in[0];
    const float* rw      = (const float*)d_in[1];
    const float* gate_w  = (const float*)d_in[2];
    const float* up_w    = (const float*)d_in[3];
    const float* down_w  = (const float*)d_in[4];
    const float* sgate_w = (const float*)d_in[5];
    const float* sup_w   = (const float*)d_in[6];
    const float* sdown_w = (const float*)d_in[7];
    float* out = (float*)d_out;

    // fused gu smem: A 2*128*12 float2 + B 2*2*16*LDN floats
    const int smem_gu = (2 * 128 * A_ST2 * 2 + 2 * 2 * 16 * LDN) * 4;
    cudaFuncSetAttribute(gemm_gu_fused,
                         cudaFuncAttributeMaxDynamicSharedMemorySize, smem_gu);

    cudaMemsetAsync(out, 0, (size_t)T_TOK * HDIM * sizeof(float));

    zero_counts_kernel<<<1, 32>>>();
    router_kernel<<<ROUTER_BLOCKS, 256>>>(x, rw, out);
    finalize_kernel<<<1, 288>>>(out);
    compact_kernel<<<((NEXP + 1) * T_TOK) / 256, 256>>>();

    dim3 grid_gu(IDIM / 128, T_TOK / 128, NEXP + 1);
    gemm_gu_fused<<<grid_gu, 256, smem_gu>>>(x, gate_w, up_w, sgate_w, sup_w);

    dim3 grid_dn(HDIM / 128, T_TOK / 128, NEXP + 1);
    gemm_down_tf32<<<grid_dn, 128>>>(down_w, sdown_w, out);
}